// round 8
// baseline (speedup 1.0000x reference)
#include <cuda_runtime.h>
#include <math.h>

#define T      4096
#define P      8
#define DM     256
#define DF     4096
#define DK     1024
#define NE     9
#define NBLK   148
#define NTHR   512

typedef unsigned long long ull;

// ---------------- scratch --------------------------------------------------
__device__ float    g_xlast[DF];
__device__ float    g_q[DK];
__device__ float    g_u[DF];
__device__ float    g_fs1[2048],  g_fc1[2048];
__device__ float    g_fs16[2048], g_fc16[2048];
__device__ float    g_fs64[2048], g_fc64[2048];
__device__ float    g_scores[T];
__device__ float    g_wtab[144];
__device__ float    g_pc[DF];
__device__ float    g_ov[DK];
__device__ float    g_oacc[DK];
__device__ float    g_Z;
__device__ unsigned g_menc;
__device__ unsigned g_bar;          // monotonic
__device__ int      g_io[T * P];
__device__ int      g_id[T * P];

#define LN1E4_OVER_2048 (9.210340371976184 / 2048.0)

// ---------------- f32x2 helpers -------------------------------------------
__device__ __forceinline__ ull pk2(float a, float b) {
    ull r; asm("mov.b64 %0, {%1, %2};" : "=l"(r) : "f"(a), "f"(b)); return r;
}
__device__ __forceinline__ float2 upk(ull x) {
    float2 r; asm("mov.b64 {%0, %1}, %2;" : "=f"(r.x), "=f"(r.y) : "l"(x)); return r;
}
__device__ __forceinline__ ull FMA2(ull a, ull b, ull c) {
    ull d; asm("fma.rn.f32x2 %0, %1, %2, %3;" : "=l"(d) : "l"(a), "l"(b), "l"(c)); return d;
}
__device__ __forceinline__ ull MUL2(ull a, ull b) {
    ull d; asm("mul.rn.f32x2 %0, %1, %2;" : "=l"(d) : "l"(a), "l"(b)); return d;
}
__device__ __forceinline__ ull ADD2(ull a, ull b) {
    ull d; asm("add.rn.f32x2 %0, %1, %2;" : "=l"(d) : "l"(a), "l"(b)); return d;
}
__device__ __forceinline__ ull NEG2(ull a) { return a ^ 0x8000000080000000ULL; }

__device__ __forceinline__ unsigned fenc(float f) {
    unsigned b = __float_as_uint(f);
    return (b & 0x80000000u) ? ~b : (b | 0x80000000u);
}
__device__ __forceinline__ float fdec(unsigned e) {
    unsigned b = (e & 0x80000000u) ? (e & 0x7fffffffu) : ~e;
    return __uint_as_float(b);
}

// leader-only-fence grid barrier (CG pattern), monotonic counter
__device__ __forceinline__ void gridbar() {
    __syncthreads();
    if (threadIdx.x == 0) {
        asm volatile("fence.acq_rel.gpu;" ::: "memory");
        unsigned my = atomicAdd(&g_bar, 1u) + 1u;
        unsigned target = ((my + NBLK - 1u) / NBLK) * NBLK;
        unsigned cur;
        for (;;) {
            asm volatile("ld.acquire.gpu.u32 %0, [%1];" : "=r"(cur) : "l"(&g_bar) : "memory");
            if ((int)(cur - target) >= 0) break;
            __nanosleep(32);
        }
    }
    __syncthreads();
}

// scalar rotpow (branch-free select), B bits
template <int B>
__device__ __forceinline__ void rotpow_s(float ps, float pc, unsigned n,
                                         float& so, float& co) {
    float s = 0.f, c = 1.f;
#pragma unroll
    for (int b = 0; b < B; b++) {
        float ns = fmaf(s, pc, c * ps);
        float nc = fmaf(c, pc, -s * ps);
        bool tk = (n >> b) & 1u;
        s = tk ? ns : s; c = tk ? nc : c;
        float t2 = 2.f * ps * pc;
        pc = fmaf(pc, pc, -ps * ps);
        ps = t2;
    }
    so = s; co = c;
}

// packed rotpow, n uniform across both lanes
template <int B>
__device__ __forceinline__ void rotpow_pk(ull ps, ull pc, unsigned n,
                                          ull& so, ull& co) {
    ull s = pk2(0.f, 0.f), c = pk2(1.f, 1.f);
#pragma unroll
    for (int b = 0; b < B; b++) {
        if ((n >> b) & 1u) {
            ull ns = FMA2(s, pc, MUL2(c, ps));
            ull nc = FMA2(c, pc, NEG2(MUL2(s, ps)));
            s = ns; c = nc;
        }
        ull td = MUL2(ps, pc);
        ull npc = FMA2(pc, pc, NEG2(MUL2(ps, ps)));
        ps = ADD2(td, td); pc = npc;
    }
    so = s; co = c;
}

// colmv: y[k] += sum_d shx[d]*W[d,k]; per-half vCTAs, 2-row chunks, 3-deep ring
__device__ __forceinline__ void colmv3(const float* __restrict__ W,
                                       const float* __restrict__ shx,
                                       float* __restrict__ y, int nvb,
                                       float* sh_acc) {
    int tid = threadIdx.x;
    int htid = tid & 255, half = tid >> 8;
    const float4* W4 = (const float4*)W;
    const int STR = 2 * NBLK;
    int v0 = blockIdx.x * 2 + half;
    float4 w0a, w0b, w1a, w1b, w2a, w2b;
    float  x0a, x0b, x1a, x1b, x2a, x2b;
    float4 acc = make_float4(0.f, 0.f, 0.f, 0.f);
    {
        int v = v0;
        if (v < nvb) {
            w0a = __ldg(&W4[(size_t)(v * 2 + 0) * 256 + htid]);
            w0b = __ldg(&W4[(size_t)(v * 2 + 1) * 256 + htid]);
            x0a = shx[v * 2]; x0b = shx[v * 2 + 1];
        }
        v = v0 + STR;
        if (v < nvb) {
            w1a = __ldg(&W4[(size_t)(v * 2 + 0) * 256 + htid]);
            w1b = __ldg(&W4[(size_t)(v * 2 + 1) * 256 + htid]);
            x1a = shx[v * 2]; x1b = shx[v * 2 + 1];
        }
        v = v0 + 2 * STR;
        if (v < nvb) {
            w2a = __ldg(&W4[(size_t)(v * 2 + 0) * 256 + htid]);
            w2b = __ldg(&W4[(size_t)(v * 2 + 1) * 256 + htid]);
            x2a = shx[v * 2]; x2b = shx[v * 2 + 1];
        }
    }
#pragma unroll
    for (int i = 0; i < 7; i++) {
        int vc = v0 + i * STR;
        int vn = v0 + (i + 3) * STR;
        float4 wa, wb; float xa, xb;
        int slot = i % 3;
        if (slot == 0) { wa = w0a; wb = w0b; xa = x0a; xb = x0b; }
        else if (slot == 1) { wa = w1a; wb = w1b; xa = x1a; xb = x1b; }
        else { wa = w2a; wb = w2b; xa = x2a; xb = x2b; }
        if (vn < nvb) {
            float4 na = __ldg(&W4[(size_t)(vn * 2 + 0) * 256 + htid]);
            float4 nb = __ldg(&W4[(size_t)(vn * 2 + 1) * 256 + htid]);
            float nxa = shx[vn * 2], nxb = shx[vn * 2 + 1];
            if (slot == 0) { w0a = na; w0b = nb; x0a = nxa; x0b = nxb; }
            else if (slot == 1) { w1a = na; w1b = nb; x1a = nxa; x1b = nxb; }
            else { w2a = na; w2b = nb; x2a = nxa; x2b = nxb; }
        }
        if (vc < nvb) {
            acc.x = fmaf(xa, wa.x, acc.x); acc.y = fmaf(xa, wa.y, acc.y);
            acc.z = fmaf(xa, wa.z, acc.z); acc.w = fmaf(xa, wa.w, acc.w);
            acc.x = fmaf(xb, wb.x, acc.x); acc.y = fmaf(xb, wb.y, acc.y);
            acc.z = fmaf(xb, wb.z, acc.z); acc.w = fmaf(xb, wb.w, acc.w);
        }
    }
    if (half == 1) ((float4*)sh_acc)[htid] = acc;
    __syncthreads();
    if (half == 0) {
        float4 o = ((float4*)sh_acc)[htid];
        atomicAdd(&y[4 * htid + 0], acc.x + o.x);
        atomicAdd(&y[4 * htid + 1], acc.y + o.y);
        atomicAdd(&y[4 * htid + 2], acc.z + o.z);
        atomicAdd(&y[4 * htid + 3], acc.w + o.w);
    }
}

__global__ void __launch_bounds__(NTHR, 1)
uber_kernel(const int* __restrict__ obs,
            const float* __restrict__ oe, const float* __restrict__ de,
            const float* __restrict__ WQ, const float* __restrict__ WK,
            const float* __restrict__ WV, const float* __restrict__ WO,
            const float* __restrict__ Wo, const float* __restrict__ bo,
            const float* __restrict__ Wd, const float* __restrict__ bd,
            const float* __restrict__ Wv, const float* __restrict__ bv,
            float* __restrict__ out, int out_size) {
    __shared__ float sh_big[8192];      // 32KB, reused per phase
    __shared__ float sh_tab[144];
    __shared__ float sh_red[16];

    int tid = threadIdx.x, bid = blockIdx.x;
    int wid = tid >> 5, lane = tid & 31;
    int half = tid >> 8, htid = tid & 255;
    int g = bid * NTHR + tid;

    // ===== P0: trig tables (double), idx, zeros, xlast ======================
    if (g < 2048) {
        double fij = exp(-(double)g * LN1E4_OVER_2048);
        double ds, dc;
        sincos(fij, &ds, &dc);        g_fs1[g] = (float)ds;  g_fc1[g] = (float)dc;
        sincos(16.0 * fij, &ds, &dc); g_fs16[g] = (float)ds; g_fc16[g] = (float)dc;
        sincos(64.0 * fij, &ds, &dc); g_fs64[g] = (float)ds; g_fc64[g] = (float)dc;
    }
    if (g < T * P) {
        const int* r0 = obs + (size_t)(2 * g) * NE;
        int io = 0, id = 0;
#pragma unroll
        for (int e = 0; e < NE; e++) {
            if (r0[e])      io = e;
            if (r0[NE + e]) id = e;
        }
        g_io[g] = io; g_id[g] = id;
    }
    if (g < DF) {
        if (g < DK) { g_q[g] = 0.f; g_ov[g] = 0.f; g_oacc[g] = 0.f; }
        if (g < 144) g_wtab[g] = 0.f;
        if (g == 0) { g_menc = 0u; g_Z = 0.f; }
        int d = g, p = d >> 9, r = d & 511;
        int row = 2 * ((T - 1) * P + p) + (r >= DM ? 1 : 0);
        const int* ro = obs + (size_t)row * NE;
        int idx = 0;
#pragma unroll
        for (int e = 0; e < NE; e++) if (ro[e]) idx = e;
        float ev = (r < DM) ? oe[idx * DM + r] : de[idx * DM + (r - DM)];
        int j = d >> 1;
        float fij = (float)exp(-(double)j * LN1E4_OVER_2048);
        float s1, c1; sincosf(fij, &s1, &c1);
        float s, c; rotpow_s<12>(s1, c1, T - 1, s, c);
        g_xlast[d] = 16.0f * ev + ((d & 1) ? c : s);
    }
    gridbar();

    // ===== P1: q = xlast @ WQ ==============================================
    for (int k = tid; k < DF; k += NTHR) sh_big[k] = g_xlast[k];
    __syncthreads();
    colmv3(WQ, sh_big, g_q, 2048, sh_big + 4096);
    gridbar();

    // ===== P2: u = WK @ q  (warp per row, 2 rows prefetched) ===============
    if (tid < 256) ((float4*)sh_big)[tid] = ((const float4*)g_q)[tid];
    __syncthreads();
    {
        int gw = bid * 16 + wid;            // 0..2367
        int r2 = gw + 2368;
        const float4* A = (const float4*)(WK + (size_t)gw * DK);
        const float4* B = (const float4*)(WK + (size_t)(r2 < 4096 ? r2 : gw) * DK);
        float4 wa[8], wb[8];
#pragma unroll
        for (int i = 0; i < 8; i++) wa[i] = __ldg(&A[lane + 32 * i]);
#pragma unroll
        for (int i = 0; i < 8; i++) wb[i] = __ldg(&B[lane + 32 * i]);
        float accA = 0.f, accB = 0.f;
#pragma unroll
        for (int i = 0; i < 8; i++) {
            float4 v = ((float4*)sh_big)[lane + 32 * i];
            accA = fmaf(wa[i].x, v.x, accA); accA = fmaf(wa[i].y, v.y, accA);
            accA = fmaf(wa[i].z, v.z, accA); accA = fmaf(wa[i].w, v.w, accA);
            accB = fmaf(wb[i].x, v.x, accB); accB = fmaf(wb[i].y, v.y, accB);
            accB = fmaf(wb[i].z, v.z, accB); accB = fmaf(wb[i].w, v.w, accB);
        }
#pragma unroll
        for (int o = 16; o; o >>= 1) {
            accA += __shfl_xor_sync(0xffffffffu, accA, o);
            accB += __shfl_xor_sync(0xffffffffu, accB, o);
        }
        if (!lane) {
            g_u[gw] = accA;
            if (r2 < 4096) g_u[r2] = accB;
        }
    }
    gridbar();

    // ===== P3: utab + scores (f32x2 packed) + running max ==================
    if (bid < 128) {
        for (int ent = wid; ent < 144; ent += 16) {
            int kind = ent / 72, p = (ent % 72) / 9, e = ent % 9;
            const float4* e4 = (const float4*)((kind ? de : oe) + e * DM);
            const float4* u4 = (const float4*)(g_u + p * 512 + kind * DM);
            float acc = 0.f;
#pragma unroll
            for (int i = 0; i < 2; i++) {
                float4 a = __ldg(&e4[lane + 32 * i]);
                float4 b = u4[lane + 32 * i];
                acc += a.x * b.x + a.y * b.y + a.z * b.z + a.w * b.w;
            }
#pragma unroll
            for (int o = 16; o; o >>= 1) acc += __shfl_xor_sync(0xffffffffu, acc, o);
            if (!lane) sh_tab[ent] = acc;
        }

        unsigned n16 = 2 * bid + half;      // t0h = 16*n16
        ull s2[4], c2[4], c1d[4], s1d[4], ns1d[4], us2[4], uc2[4];
#pragma unroll
        for (int q = 0; q < 4; q++) {
            int ja = htid + 256 * q, jb = ja + 1024;
            float2 ua = ((const float2*)g_u)[ja];
            float2 ub = ((const float2*)g_u)[jb];
            us2[q] = pk2(ua.x, ub.x); uc2[q] = pk2(ua.y, ub.y);
            c1d[q] = pk2(g_fc1[ja], g_fc1[jb]);
            s1d[q] = pk2(g_fs1[ja], g_fs1[jb]);
            ns1d[q] = NEG2(s1d[q]);
            ull ps = pk2(g_fs16[ja], g_fs16[jb]);
            ull pc = pk2(g_fc16[ja], g_fc16[jb]);
            rotpow_pk<8>(ps, pc, n16, s2[q], c2[q]);
        }
        __syncthreads();
        const ull Z2 = pk2(0.f, 0.f);
        for (int n = 0; n < 16; n++) {
            ull part2 = Z2;
#pragma unroll
            for (int q = 0; q < 4; q++) {
                part2 = FMA2(us2[q], s2[q], part2);
                part2 = FMA2(uc2[q], c2[q], part2);
            }
            float2 pp = upk(part2);
            sh_big[(half * 16 + n) * 256 + htid] = pp.x + pp.y;
#pragma unroll
            for (int q = 0; q < 4; q++) {
                ull ns = FMA2(s2[q], c1d[q], MUL2(c2[q], s1d[q]));
                ull nc = FMA2(c2[q], c1d[q], MUL2(s2[q], ns1d[q]));
                s2[q] = ns; c2[q] = nc;
            }
        }
        __syncthreads();
#pragma unroll
        for (int rr = 0; rr < 2; rr++) {
            int r = wid * 2 + rr;
            float v = 0.f;
#pragma unroll
            for (int i = 0; i < 8; i++) v += sh_big[r * 256 + lane + 32 * i];
#pragma unroll
            for (int o = 16; o; o >>= 1) v += __shfl_xor_sync(0xffffffffu, v, o);
            if (!lane) {
                int t = bid * 32 + r;
                float es = 0.f;
#pragma unroll
                for (int p = 0; p < P; p++)
                    es += sh_tab[p * 9 + g_io[t * P + p]] + sh_tab[72 + p * 9 + g_id[t * P + p]];
                float sc = fmaf(16.0f, es, v);
                g_scores[t] = sc;
                atomicMax(&g_menc, fenc(sc));
            }
        }
    }
    gridbar();

    // ===== P4: pc (no atomics, packed) | wtab + Z ==========================
    if (bid < 128) {
        float m = fdec(g_menc);
#pragma unroll
        for (int k = 0; k < 8; k++) {
            int t = tid * 8 + k;
            float e = __expf(fmaf(g_scores[t], 1.0f / 32.0f, -m));
            sh_big[(t & 63) * 64 + (t >> 6)] = e;
        }
        __syncthreads();
        int j = bid * 16 + wid;             // 0..2047
        ull c1d = pk2(g_fc1[j], g_fc1[j]);
        ull s1d = pk2(g_fs1[j], g_fs1[j]);
        ull ns1d = NEG2(s1d);
        float sa, ca;
        rotpow_s<8>(g_fs16[j], g_fc16[j], 8u * lane, sa, ca);
        float s64 = g_fs64[j], c64 = g_fc64[j];
        float sb = fmaf(sa, c64, ca * s64);
        float cb = fmaf(ca, c64, -sa * s64);
        ull s2 = pk2(sa, sb), c2 = pk2(ca, cb);
        ull as2 = pk2(0.f, 0.f), ac2 = as2;
        const float* she = sh_big;
        for (int n = 0; n < 64; n++) {
            float2 ev = *(const float2*)&she[n * 64 + 2 * lane];
            ull w2 = pk2(ev.x, ev.y);
            as2 = FMA2(w2, s2, as2);
            ac2 = FMA2(w2, c2, ac2);
            ull ns = FMA2(s2, c1d, MUL2(c2, s1d));
            ull nc = FMA2(c2, c1d, MUL2(s2, ns1d));
            s2 = ns; c2 = nc;
        }
        float2 aa = upk(as2), bb = upk(ac2);
        float as = aa.x + aa.y, ac = bb.x + bb.y;
#pragma unroll
        for (int o = 16; o; o >>= 1) {
            as += __shfl_xor_sync(0xffffffffu, as, o);
            ac += __shfl_xor_sync(0xffffffffu, ac, o);
        }
        if (!lane) { g_pc[2 * j] = as; g_pc[2 * j + 1] = ac; }
    } else {
        int b2 = bid - 128;                 // 0..19
        int tlo = b2 * 205, thi = min(4096, tlo + 205);
        float m = fdec(g_menc);
        if (tid < 144) sh_tab[tid] = 0.f;
        __syncthreads();
        for (int k = tid; k < (thi - tlo) * 8; k += NTHR) {
            int t = tlo + (k >> 3), p = k & 7;
            float w = __expf(fmaf(g_scores[t], 1.0f / 32.0f, -m));
            atomicAdd(&sh_tab[p * 9 + g_io[t * P + p]], w);
            atomicAdd(&sh_tab[72 + p * 9 + g_id[t * P + p]], w);
        }
        float zp = 0.f;
        for (int t = tlo + tid; t < thi; t += NTHR)
            zp += __expf(fmaf(g_scores[t], 1.0f / 32.0f, -m));
#pragma unroll
        for (int o = 16; o; o >>= 1) zp += __shfl_xor_sync(0xffffffffu, zp, o);
        if (!lane) sh_red[wid] = zp;
        __syncthreads();
        if (tid == 0) {
            float z = 0.f;
#pragma unroll
            for (int i = 0; i < 16; i++) z += sh_red[i];
            atomicAdd(&g_Z, z);
        }
        if (tid < 144) atomicAdd(&g_wtab[tid], sh_tab[tid]);
    }
    gridbar();

    // ===== P5: build c in smem, ov = c @ WV ================================
    if (tid < 144) sh_tab[tid] = g_wtab[tid];
    __syncthreads();
    for (int k = tid; k < DF; k += NTHR) {
        int d = k, p = d >> 9, r = d & 511;
        float a = 0.f;
        if (r < DM) {
#pragma unroll
            for (int e = 0; e < NE; e++) a = fmaf(sh_tab[p * 9 + e], __ldg(&oe[e * DM + r]), a);
        } else {
            int rr = r - DM;
#pragma unroll
            for (int e = 0; e < NE; e++) a = fmaf(sh_tab[72 + p * 9 + e], __ldg(&de[e * DM + rr]), a);
        }
        sh_big[k] = fmaf(16.0f, a, g_pc[d]);
    }
    __syncthreads();
    colmv3(WV, sh_big, g_ov, 2048, sh_big + 4096);
    gridbar();

    // ===== P6: oacc = ov @ WO ==============================================
    for (int k = tid; k < DK; k += NTHR) sh_big[k] = g_ov[k];
    __syncthreads();
    colmv3(WO, sh_big, g_oacc, 512, sh_big + 4096);
    gridbar();

    // ===== P7: heads =======================================================
    if (bid < 129) {
        const float* Wr; float bias;
        if (bid < 64)       { Wr = Wo + bid * DK;        bias = bo[bid]; }
        else if (bid < 128) { Wr = Wd + (bid - 64) * DK; bias = bd[bid - 64]; }
        else                { Wr = Wv;                   bias = bv[0]; }
        float acc = 0.f;
        if (tid < 256) {
            float4 h4 = ((const float4*)g_oacc)[tid];
            float4 w4 = __ldg(&((const float4*)Wr)[tid]);
            acc = fmaxf(h4.x, 0.f) * w4.x + fmaxf(h4.y, 0.f) * w4.y +
                  fmaxf(h4.z, 0.f) * w4.z + fmaxf(h4.w, 0.f) * w4.w;
        }
#pragma unroll
        for (int o = 16; o; o >>= 1) acc += __shfl_xor_sync(0xffffffffu, acc, o);
        if (!lane && wid < 8) sh_red[wid] = acc;
        __syncthreads();
        if (tid == 0 && bid < out_size) {
            float sum = 0.f;
#pragma unroll
            for (int i = 0; i < 8; i++) sum += sh_red[i];
            out[bid] = sum * (1.0f / g_Z) + bias;
        }
    }
}

// ---------------- host launcher ---------------------------------------------
extern "C" void kernel_launch(void* const* d_in, const int* in_sizes, int n_in,
                              void* d_out, int out_size) {
    const int*   obs = (const int*)d_in[0];
    const float* oe  = (const float*)d_in[1];
    const float* de  = (const float*)d_in[2];
    const float* WQ  = (const float*)d_in[3];
    const float* WK  = (const float*)d_in[4];
    const float* WV  = (const float*)d_in[5];
    const float* WO  = (const float*)d_in[6];
    const float* Wo  = (const float*)d_in[7];
    const float* bo  = (const float*)d_in[8];
    const float* Wd  = (const float*)d_in[9];
    const float* bd  = (const float*)d_in[10];
    const float* Wv  = (const float*)d_in[11];
    const float* bv  = (const float*)d_in[12];
    float* out = (float*)d_out;

    uber_kernel<<<NBLK, NTHR>>>(obs, oe, de, WQ, WK, WV, WO,
                                Wo, bo, Wd, bd, Wv, bv, out, out_size);
}

// round 10
// speedup vs baseline: 1.0984x; 1.0984x over previous
#include <cuda_runtime.h>
#include <math.h>

#define T      4096
#define P      8
#define DM     256
#define DF     4096
#define DK     1024
#define NE     9
#define NBLK   148
#define NTHR   512

typedef unsigned long long ull;

// ---------------- scratch --------------------------------------------------
__device__ float    g_q[DK];
__device__ float    g_u[DF];
__device__ float    g_fs1[2048],  g_fc1[2048];
__device__ float    g_fs16[2048], g_fc16[2048];
__device__ float    g_fs64[2048], g_fc64[2048];
__device__ float    g_scores[T];
__device__ float    g_wtab[144];
__device__ float    g_pc[DF];
__device__ float    g_ov[DK];
__device__ float    g_oacc[DK];
__device__ float    g_Z;
__device__ unsigned g_menc;
__device__ unsigned g_bar;
__device__ int      g_io[T * P];
__device__ int      g_id[T * P];

#define LN1E4_OVER_2048 (9.210340371976184 / 2048.0)

// ---------------- f32x2 helpers -------------------------------------------
__device__ __forceinline__ ull pk2(float a, float b) {
    ull r; asm("mov.b64 %0, {%1, %2};" : "=l"(r) : "f"(a), "f"(b)); return r;
}
__device__ __forceinline__ float2 upk(ull x) {
    float2 r; asm("mov.b64 {%0, %1}, %2;" : "=f"(r.x), "=f"(r.y) : "l"(x)); return r;
}
__device__ __forceinline__ ull FMA2(ull a, ull b, ull c) {
    ull d; asm("fma.rn.f32x2 %0, %1, %2, %3;" : "=l"(d) : "l"(a), "l"(b), "l"(c)); return d;
}
__device__ __forceinline__ ull MUL2(ull a, ull b) {
    ull d; asm("mul.rn.f32x2 %0, %1, %2;" : "=l"(d) : "l"(a), "l"(b)); return d;
}
__device__ __forceinline__ ull NEG2(ull a) { return a ^ 0x8000000080000000ULL; }

__device__ __forceinline__ unsigned fenc(float f) {
    unsigned b = __float_as_uint(f);
    return (b & 0x80000000u) ? ~b : (b | 0x80000000u);
}
__device__ __forceinline__ float fdec(unsigned e) {
    unsigned b = (e & 0x80000000u) ? (e & 0x7fffffffu) : ~e;
    return __uint_as_float(b);
}

// ---------------- cp.async helpers -----------------------------------------
__device__ __forceinline__ void cpa16(void* dst, const void* src) {
    unsigned d = (unsigned)__cvta_generic_to_shared(dst);
    asm volatile("cp.async.cg.shared.global [%0], [%1], 16;" :: "r"(d), "l"(src));
}
__device__ __forceinline__ void cpa_commit() {
    asm volatile("cp.async.commit_group;" ::: "memory");
}
__device__ __forceinline__ void cpa_wait3() {
    asm volatile("cp.async.wait_group 3;" ::: "memory");
}
__device__ __forceinline__ void cpa_wait0() {
    asm volatile("cp.async.wait_group 0;" ::: "memory");
}

// issue one 16KB tile (4 rows x 1024 f32) of W chunk `ch` into stage buffer
__device__ __forceinline__ void issue_tile(const float* __restrict__ W,
                                           float* stagebuf, int ch, int nch, int tid) {
    if (ch < nch) {
        const float4* src = (const float4*)W + (size_t)ch * 1024;
        float4* dst = (float4*)stagebuf;
        cpa16(dst + tid, src + tid);
        cpa16(dst + tid + 512, src + tid + 512);
    }
    cpa_commit();
}

// leader-only-fence grid barrier, monotonic counter
__device__ __forceinline__ void gridbar() {
    __syncthreads();
    if (threadIdx.x == 0) {
        asm volatile("fence.acq_rel.gpu;" ::: "memory");
        unsigned my = atomicAdd(&g_bar, 1u) + 1u;
        unsigned target = ((my + NBLK - 1u) / NBLK) * NBLK;
        unsigned cur;
        for (;;) {
            asm volatile("ld.acquire.gpu.u32 %0, [%1];" : "=r"(cur) : "l"(&g_bar) : "memory");
            if ((int)(cur - target) >= 0) break;
            __nanosleep(32);
        }
    }
    __syncthreads();
}

// scalar rotpow (branch-free select), B bits
template <int B>
__device__ __forceinline__ void rotpow_s(float ps, float pc, unsigned n,
                                         float& so, float& co) {
    float s = 0.f, c = 1.f;
#pragma unroll
    for (int b = 0; b < B; b++) {
        float ns = fmaf(s, pc, c * ps);
        float nc = fmaf(c, pc, -s * ps);
        bool tk = (n >> b) & 1u;
        s = tk ? ns : s; c = tk ? nc : c;
        float t2 = 2.f * ps * pc;
        pc = fmaf(pc, pc, -ps * ps);
        ps = t2;
    }
    so = s; co = c;
}

// packed rotpow, n uniform
template <int B>
__device__ __forceinline__ void rotpow_pk(ull ps, ull pc, unsigned n,
                                          ull& so, ull& co) {
    ull s = pk2(0.f, 0.f), c = pk2(1.f, 1.f);
#pragma unroll
    for (int b = 0; b < B; b++) {
        if ((n >> b) & 1u) {
            ull ns = FMA2(s, pc, MUL2(c, ps));
            ull nc = FMA2(c, pc, NEG2(MUL2(s, ps)));
            s = ns; c = nc;
        }
        ull td = MUL2(ps, pc);
        ull npc = FMA2(pc, pc, NEG2(MUL2(ps, ps)));
        ps = td + td - (((td + td) ^ td) & 0ULL); // placeholder avoided below
        ps = td; // will fix with ADD
        // proper double-angle: ps = 2*ps*pc
        {
            ull two = pk2(2.f, 2.f);
            ps = MUL2(two, td);
        }
        pc = npc;
    }
    so = s; co = c;
}

// ---------------- pre kernel: zeros, trig tables, io/id ---------------------
__global__ void pre_kernel(const int* __restrict__ obs) {
    int g = blockIdx.x * blockDim.x + threadIdx.x;
    if (g < 2048) {
        double fij = exp(-(double)g * LN1E4_OVER_2048);
        double ds, dc;
        sincos(fij, &ds, &dc);        g_fs1[g] = (float)ds;  g_fc1[g] = (float)dc;
        sincos(16.0 * fij, &ds, &dc); g_fs16[g] = (float)ds; g_fc16[g] = (float)dc;
        sincos(64.0 * fij, &ds, &dc); g_fs64[g] = (float)ds; g_fc64[g] = (float)dc;
    }
    if (g < T * P) {
        const int* r0 = obs + (size_t)(2 * g) * NE;
        int io = 0, id = 0;
#pragma unroll
        for (int e = 0; e < NE; e++) {
            if (r0[e])      io = e;
            if (r0[NE + e]) id = e;
        }
        g_io[g] = io;
        g_id[g] = id;
    }
    if (g < DK) { g_q[g] = 0.f; g_ov[g] = 0.f; g_oacc[g] = 0.f; }
    if (g < 144) g_wtab[g] = 0.f;
    if (g == 0) { g_menc = 0u; g_Z = 0.f; g_bar = 0u; }
}

// ---------------- uber kernel ----------------------------------------------
// dynamic smem layout (floats):
//   sh_x    [4096]        x vector for matvec phases
//   stage   [16384]       4 stages x 4096  (reused as sh_big 8192 in P3/P4)
//   sh_acc  [1024]
//   sh_tab  [160]
//   sh_red  [32]
#define SMEM_FLOATS (4096 + 16384 + 1024 + 160 + 32)

__global__ void __launch_bounds__(NTHR, 1)
uber_kernel(const int* __restrict__ obs,
            const float* __restrict__ oe, const float* __restrict__ de,
            const float* __restrict__ WQ, const float* __restrict__ WK,
            const float* __restrict__ WV, const float* __restrict__ WO,
            const float* __restrict__ Wo, const float* __restrict__ bo,
            const float* __restrict__ Wd, const float* __restrict__ bd,
            const float* __restrict__ Wv, const float* __restrict__ bv,
            float* __restrict__ out, int out_size) {
    extern __shared__ float smem[];
    float* sh_x   = smem;
    float* stage  = smem + 4096;
    float* sh_acc = smem + 4096 + 16384;
    float* sh_tab = sh_acc + 1024;
    float* sh_red = sh_tab + 160;
    float* sh_big = stage;              // alias for P3/P4

    int tid = threadIdx.x, bid = blockIdx.x;
    int wid = tid >> 5, lane = tid & 31;
    int half = tid >> 8, htid = tid & 255;

    // ===== P1: WQ prologue; build xlast in smem; colmv loop ================
#pragma unroll
    for (int s = 0; s < 4; s++)
        issue_tile(WQ, stage + s * 4096, bid + s * NBLK, 1024, tid);

    for (int k = tid; k < DF; k += NTHR) {
        int d = k, p = d >> 9, r = d & 511;
        int row = 2 * ((T - 1) * P + p) + (r >= DM ? 1 : 0);
        const int* ro = obs + (size_t)row * NE;
        int idx = 0;
#pragma unroll
        for (int e = 0; e < NE; e++) if (ro[e]) idx = e;
        float ev = (r < DM) ? oe[idx * DM + r] : de[idx * DM + (r - DM)];
        int j = d >> 1;
        float s1 = g_fs1[j], c1 = g_fc1[j];
        float s, c; rotpow_s<12>(s1, c1, T - 1, s, c);
        sh_x[k] = 16.0f * ev + ((d & 1) ? c : s);
    }
    __syncthreads();
    {
        float4 acc = make_float4(0.f, 0.f, 0.f, 0.f);
        int it = 0;
        for (int ch = bid; ch < 1024; ch += NBLK, it++) {
            cpa_wait3();
            __syncthreads();
            const float* sw = stage + (it & 3) * 4096;
            float xa = sh_x[ch * 4 + 2 * half];
            float xb = sh_x[ch * 4 + 2 * half + 1];
            float4 wa = ((const float4*)sw)[(2 * half) * 256 + htid];
            float4 wb = ((const float4*)sw)[(2 * half + 1) * 256 + htid];
            acc.x = fmaf(xa, wa.x, acc.x); acc.y = fmaf(xa, wa.y, acc.y);
            acc.z = fmaf(xa, wa.z, acc.z); acc.w = fmaf(xa, wa.w, acc.w);
            acc.x = fmaf(xb, wb.x, acc.x); acc.y = fmaf(xb, wb.y, acc.y);
            acc.z = fmaf(xb, wb.z, acc.z); acc.w = fmaf(xb, wb.w, acc.w);
            __syncthreads();
            issue_tile(WQ, stage + (it & 3) * 4096, ch + 4 * NBLK, 1024, tid);
        }
        cpa_wait0();
        __syncthreads();
        if (half == 1) ((float4*)sh_acc)[htid] = acc;
        // prefetch WK prologue across the barrier
#pragma unroll
        for (int s = 0; s < 4; s++)
            issue_tile(WK, stage + s * 4096, bid + s * NBLK, 1024, tid);
        __syncthreads();
        if (half == 0) {
            float4 o = ((float4*)sh_acc)[htid];
            atomicAdd(&g_q[4 * htid + 0], acc.x + o.x);
            atomicAdd(&g_q[4 * htid + 1], acc.y + o.y);
            atomicAdd(&g_q[4 * htid + 2], acc.z + o.z);
            atomicAdd(&g_q[4 * htid + 3], acc.w + o.w);
        }
    }
    gridbar();

    // ===== P2: u = WK @ q (row dots from smem tiles) =======================
    if (tid < 256) ((float4*)sh_x)[tid] = ((const float4*)g_q)[tid];
    __syncthreads();
    {
        int rloc = wid & 3, qd = wid >> 2;
        int it = 0;
        for (int ch = bid; ch < 1024; ch += NBLK, it++) {
            cpa_wait3();
            __syncthreads();
            const float* sw = stage + (it & 3) * 4096;
            const float4* wr = (const float4*)(sw + rloc * 1024);
            const float4* q4 = (const float4*)sh_x;
            int i0 = qd * 64 + lane;
            float4 a = wr[i0], b = wr[i0 + 32];
            float4 va = q4[i0], vb = q4[i0 + 32];
            float acc = a.x * va.x + a.y * va.y + a.z * va.z + a.w * va.w
                      + b.x * vb.x + b.y * vb.y + b.z * vb.z + b.w * vb.w;
#pragma unroll
            for (int o = 16; o; o >>= 1) acc += __shfl_xor_sync(0xffffffffu, acc, o);
            if (!lane) sh_red[rloc * 4 + qd] = acc;
            __syncthreads();
            if (tid < 4)
                g_u[ch * 4 + tid] = sh_red[tid * 4 + 0] + sh_red[tid * 4 + 1]
                                  + sh_red[tid * 4 + 2] + sh_red[tid * 4 + 3];
            issue_tile(WK, stage + (it & 3) * 4096, ch + 4 * NBLK, 1024, tid);
        }
        cpa_wait0();
    }
    gridbar();

    // ===== P3: utab + scores (packed) + running max ========================
    if (bid < 128) {
        for (int ent = wid; ent < 144; ent += 16) {
            int kind = ent / 72, p = (ent % 72) / 9, e = ent % 9;
            const float4* e4 = (const float4*)((kind ? de : oe) + e * DM);
            const float4* u4 = (const float4*)(g_u + p * 512 + kind * DM);
            float acc = 0.f;
#pragma unroll
            for (int i = 0; i < 2; i++) {
                float4 a = __ldg(&e4[lane + 32 * i]);
                float4 b = u4[lane + 32 * i];
                acc += a.x * b.x + a.y * b.y + a.z * b.z + a.w * b.w;
            }
#pragma unroll
            for (int o = 16; o; o >>= 1) acc += __shfl_xor_sync(0xffffffffu, acc, o);
            if (!lane) sh_tab[ent] = acc;
        }

        unsigned n16 = 2 * bid + half;
        ull s2[4], c2[4], c1d[4], s1d[4], ns1d[4], us2[4], uc2[4];
#pragma unroll
        for (int q = 0; q < 4; q++) {
            int ja = htid + 256 * q, jb = ja + 1024;
            float2 ua = ((const float2*)g_u)[ja];
            float2 ub = ((const float2*)g_u)[jb];
            us2[q] = pk2(ua.x, ub.x); uc2[q] = pk2(ua.y, ub.y);
            c1d[q] = pk2(g_fc1[ja], g_fc1[jb]);
            s1d[q] = pk2(g_fs1[ja], g_fs1[jb]);
            ns1d[q] = NEG2(s1d[q]);
            ull ps = pk2(g_fs16[ja], g_fs16[jb]);
            ull pc = pk2(g_fc16[ja], g_fc16[jb]);
            rotpow_pk<8>(ps, pc, n16, s2[q], c2[q]);
        }
        __syncthreads();
        const ull Z2 = pk2(0.f, 0.f);
        for (int n = 0; n < 16; n++) {
            ull part2 = Z2;
#pragma unroll
            for (int q = 0; q < 4; q++) {
                part2 = FMA2(us2[q], s2[q], part2);
                part2 = FMA2(uc2[q], c2[q], part2);
            }
            float2 pp = upk(part2);
            sh_big[(half * 16 + n) * 256 + htid] = pp.x + pp.y;
#pragma unroll
            for (int q = 0; q < 4; q++) {
                ull ns = FMA2(s2[q], c1d[q], MUL2(c2[q], s1d[q]));
                ull nc = FMA2(c2[q], c1d[q], MUL2(s2[q], ns1d[q]));
                s2[q] = ns; c2[q] = nc;
            }
        }
        __syncthreads();
#pragma unroll
        for (int rr = 0; rr < 2; rr++) {
            int r = wid * 2 + rr;
            float v = 0.f;
#pragma unroll
            for (int i = 0; i < 8; i++) v += sh_big[r * 256 + lane + 32 * i];
#pragma unroll
            for (int o = 16; o; o >>= 1) v += __shfl_xor_sync(0xffffffffu, v, o);
            if (!lane) {
                int t = bid * 32 + r;
                float es = 0.f;
#pragma unroll
                for (int p = 0; p < P; p++)
                    es += sh_tab[p * 9 + g_io[t * P + p]] + sh_tab[72 + p * 9 + g_id[t * P + p]];
                float sc = fmaf(16.0f, es, v);
                g_scores[t] = sc;
                atomicMax(&g_menc, fenc(sc));
            }
        }
    }
    gridbar();

    // ===== P4: pc (no atomics, packed) | wtab + Z ==========================
    if (bid < 128) {
        float m = fdec(g_menc);
#pragma unroll
        for (int k = 0; k < 8; k++) {
            int t = tid * 8 + k;
            float e = __expf(fmaf(g_scores[t], 1.0f / 32.0f, -m));
            sh_big[(t & 63) * 64 + (t >> 6)] = e;
        }
        __syncthreads();
        int j = bid * 16 + wid;
        ull c1d = pk2(g_fc1[j], g_fc1[j]);
        ull s1d = pk2(g_fs1[j], g_fs1[j]);
        ull ns1d = NEG2(s1d);
        float sa, ca;
        rotpow_s<8>(g_fs16[j], g_fc16[j], 8u * lane, sa, ca);
        float s64 = g_fs64[j], c64 = g_fc64[j];
        float sb = fmaf(sa, c64, ca * s64);
        float cb = fmaf(ca, c64, -sa * s64);
        ull s2 = pk2(sa, sb), c2 = pk2(ca, cb);
        ull as2 = pk2(0.f, 0.f), ac2 = as2;
        const float* she = sh_big;
        for (int n = 0; n < 64; n++) {
            float2 ev = *(const float2*)&she[n * 64 + 2 * lane];
            ull w2 = pk2(ev.x, ev.y);
            as2 = FMA2(w2, s2, as2);
            ac2 = FMA2(w2, c2, ac2);
            ull ns = FMA2(s2, c1d, MUL2(c2, s1d));
            ull nc = FMA2(c2, c1d, MUL2(s2, ns1d));
            s2 = ns; c2 = nc;
        }
        float2 aa = upk(as2), bb = upk(ac2);
        float as = aa.x + aa.y, ac = bb.x + bb.y;
#pragma unroll
        for (int o = 16; o; o >>= 1) {
            as += __shfl_xor_sync(0xffffffffu, as, o);
            ac += __shfl_xor_sync(0xffffffffu, ac, o);
        }
        if (!lane) { g_pc[2 * j] = as; g_pc[2 * j + 1] = ac; }
    } else {
        int b2 = bid - 128;
        int tlo = b2 * 205, thi = min(4096, tlo + 205);
        float m = fdec(g_menc);
        if (tid < 144) sh_tab[tid] = 0.f;
        __syncthreads();
        for (int k = tid; k < (thi - tlo) * 8; k += NTHR) {
            int t = tlo + (k >> 3), p = k & 7;
            float w = __expf(fmaf(g_scores[t], 1.0f / 32.0f, -m));
            atomicAdd(&sh_tab[p * 9 + g_io[t * P + p]], w);
            atomicAdd(&sh_tab[72 + p * 9 + g_id[t * P + p]], w);
        }
        float zp = 0.f;
        for (int t = tlo + tid; t < thi; t += NTHR)
            zp += __expf(fmaf(g_scores[t], 1.0f / 32.0f, -m));
#pragma unroll
        for (int o = 16; o; o >>= 1) zp += __shfl_xor_sync(0xffffffffu, zp, o);
        if (!lane) sh_red[wid] = zp;
        __syncthreads();
        if (tid == 0) {
            float z = 0.f;
#pragma unroll
            for (int i = 0; i < 16; i++) z += sh_red[i];
            atomicAdd(&g_Z, z);
        }
        if (tid < 144) atomicAdd(&g_wtab[tid], sh_tab[tid]);
    }
    // prefetch WV prologue across the barrier (stage no longer read)
    __syncthreads();
#pragma unroll
    for (int s = 0; s < 4; s++)
        issue_tile(WV, stage + s * 4096, bid + s * NBLK, 1024, tid);
    gridbar();

    // ===== P5: build c in smem; ov = c @ WV ================================
    if (tid < 144) sh_tab[tid] = g_wtab[tid];
    __syncthreads();
    for (int k = tid; k < DF; k += NTHR) {
        int d = k, p = d >> 9, r = d & 511;
        float a = 0.f;
        if (r < DM) {
#pragma unroll
            for (int e = 0; e < NE; e++) a = fmaf(sh_tab[p * 9 + e], __ldg(&oe[e * DM + r]), a);
        } else {
            int rr = r - DM;
#pragma unroll
            for (int e = 0; e < NE; e++) a = fmaf(sh_tab[72 + p * 9 + e], __ldg(&de[e * DM + rr]), a);
        }
        sh_x[k] = fmaf(16.0f, a, g_pc[d]);
    }
    __syncthreads();
    {
        float4 acc = make_float4(0.f, 0.f, 0.f, 0.f);
        int it = 0;
        for (int ch = bid; ch < 1024; ch += NBLK, it++) {
            cpa_wait3();
            __syncthreads();
            const float* sw = stage + (it & 3) * 4096;
            float xa = sh_x[ch * 4 + 2 * half];
            float xb = sh_x[ch * 4 + 2 * half + 1];
            float4 wa = ((const float4*)sw)[(2 * half) * 256 + htid];
            float4 wb = ((const float4*)sw)[(2 * half + 1) * 256 + htid];
            acc.x = fmaf(xa, wa.x, acc.x); acc.y = fmaf(xa, wa.y, acc.y);
            acc.z = fmaf(xa, wa.z, acc.z); acc.w = fmaf(xa, wa.w, acc.w);
            acc.x = fmaf(xb, wb.x, acc.x); acc.y = fmaf(xb, wb.y, acc.y);
            acc.z = fmaf(xb, wb.z, acc.z); acc.w = fmaf(xb, wb.w, acc.w);
            __syncthreads();
            issue_tile(WV, stage + (it & 3) * 4096, ch + 4 * NBLK, 1024, tid);
        }
        cpa_wait0();
        __syncthreads();
        if (half == 1) ((float4*)sh_acc)[htid] = acc;
        // prefetch WO prologue across the barrier
#pragma unroll
        for (int s = 0; s < 4; s++)
            issue_tile(WO, stage + s * 4096, bid + s * NBLK, 256, tid);
        __syncthreads();
        if (half == 0) {
            float4 o = ((float4*)sh_acc)[htid];
            atomicAdd(&g_ov[4 * htid + 0], acc.x + o.x);
            atomicAdd(&g_ov[4 * htid + 1], acc.y + o.y);
            atomicAdd(&g_ov[4 * htid + 2], acc.z + o.z);
            atomicAdd(&g_ov[4 * htid + 3], acc.w + o.w);
        }
    }
    gridbar();

    // ===== P6: oacc = ov @ WO ==============================================
    if (tid < 256) ((float4*)sh_x)[tid] = ((const float4*)g_ov)[tid];
    __syncthreads();
    {
        float4 acc = make_float4(0.f, 0.f, 0.f, 0.f);
        int it = 0;
        for (int ch = bid; ch < 256; ch += NBLK, it++) {
            cpa_wait3();
            __syncthreads();
            const float* sw = stage + (it & 3) * 4096;
            float xa = sh_x[ch * 4 + 2 * half];
            float xb = sh_x[ch * 4 + 2 * half + 1];
            float4 wa = ((const float4*)sw)[(2 * half) * 256 + htid];
            float4 wb = ((const float4*)sw)[(2 * half + 1) * 256 + htid];
            acc.x = fmaf(xa, wa.x, acc.x); acc.y = fmaf(xa, wa.y, acc.y);
            acc.z = fmaf(xa, wa.z, acc.z); acc.w = fmaf(xa, wa.w, acc.w);
            acc.x = fmaf(xb, wb.x, acc.x); acc.y = fmaf(xb, wb.y, acc.y);
            acc.z = fmaf(xb, wb.z, acc.z); acc.w = fmaf(xb, wb.w, acc.w);
            __syncthreads();
            issue_tile(WO, stage + (it & 3) * 4096, ch + 4 * NBLK, 256, tid);
        }
        cpa_wait0();
        __syncthreads();
        if (half == 1) ((float4*)sh_acc)[htid] = acc;
        __syncthreads();
        if (half == 0) {
            float4 o = ((float4*)sh_acc)[htid];
            atomicAdd(&g_oacc[4 * htid + 0], acc.x + o.x);
            atomicAdd(&g_oacc[4 * htid + 1], acc.y + o.y);
            atomicAdd(&g_oacc[4 * htid + 2], acc.z + o.z);
            atomicAdd(&g_oacc[4 * htid + 3], acc.w + o.w);
        }
    }
    gridbar();

    // ===== P7: heads =======================================================
    if (bid < 129) {
        const float* Wr; float bias;
        if (bid < 64)       { Wr = Wo + bid * DK;        bias = bo[bid]; }
        else if (bid < 128) { Wr = Wd + (bid - 64) * DK; bias = bd[bid - 64]; }
        else                { Wr = Wv;                   bias = bv[0]; }
        float acc = 0.f;
        if (tid < 256) {
            float4 h4 = ((const float4*)g_oacc)[tid];
            float4 w4 = __ldg(&((const float4*)Wr)[tid]);
            acc = fmaxf(h4.x, 0.f) * w4.x + fmaxf(h4.y, 0.f) * w4.y +
                  fmaxf(h4.z, 0.f) * w4.z + fmaxf(h4.w, 0.f) * w4.w;
        }
#pragma unroll
        for (int o = 16; o; o >>= 1) acc += __shfl_xor_sync(0xffffffffu, acc, o);
        if (!lane && wid < 8) sh_red[wid] = acc;
        __syncthreads();
        if (tid == 0 && bid < out_size) {
            float sum = 0.f;
#pragma unroll
            for (int i = 0; i < 8; i++) sum += sh_red[i];
            out[bid] = sum * (1.0f / g_Z) + bias;
        }
    }
}

// ---------------- host launcher ---------------------------------------------
extern "C" void kernel_launch(void* const* d_in, const int* in_sizes, int n_in,
                              void* d_out, int out_size) {
    const int*   obs = (const int*)d_in[0];
    const float* oe  = (const float*)d_in[1];
    const float* de  = (const float*)d_in[2];
    const float* WQ  = (const float*)d_in[3];
    const float* WK  = (const float*)d_in[4];
    const float* WV  = (const float*)d_in[5];
    const float* WO  = (const float*)d_in[6];
    const float* Wo  = (const float*)d_in[7];
    const float* bo  = (const float*)d_in[8];
    const float* Wd  = (const float*)d_in[9];
    const float* bd  = (const float*)d_in[10];
    const float* Wv  = (const float*)d_in[11];
    const float* bv  = (const float*)d_in[12];
    float* out = (float*)d_out;

    const int smem_bytes = SMEM_FLOATS * 4;
    cudaFuncSetAttribute(uber_kernel, cudaFuncAttributeMaxDynamicSharedMemorySize,
                         smem_bytes);

    pre_kernel<<<NBLK, 256>>>(obs);
    uber_kernel<<<NBLK, NTHR, smem_bytes>>>(obs, oe, de, WQ, WK, WV, WO,
                                            Wo, bo, Wd, bd, Wv, bv, out, out_size);
}

// round 12
// speedup vs baseline: 1.2546x; 1.1422x over previous
#include <cuda_runtime.h>
#include <math.h>

#define T      4096
#define P      8
#define DM     256
#define DF     4096
#define DK     1024
#define NE     9
#define NBLK   148
#define NTHR   512

// ---------------- scratch --------------------------------------------------
__device__ float    g_q[DK];
__device__ float    g_u[DF];
__device__ float    g_fs1[2048], g_fc1[2048];
__device__ float    g_wtab[144];
__device__ float    g_pc[DF];
__device__ float    g_ov[DK];
__device__ float    g_oacc[DK];
__device__ float    g_Z;
__device__ unsigned g_bar;          // monotonic, never reset
__device__ int      g_io[T * P];
__device__ int      g_id[T * P];

#define LN1E4_OVER_2048 (9.210340371976184 / 2048.0)

// leader-only-fence grid barrier, monotonic counter
__device__ __forceinline__ void gridbar() {
    __syncthreads();
    if (threadIdx.x == 0) {
        asm volatile("fence.acq_rel.gpu;" ::: "memory");
        unsigned my = atomicAdd(&g_bar, 1u) + 1u;
        unsigned target = ((my + NBLK - 1u) / NBLK) * NBLK;
        unsigned cur;
        for (;;) {
            asm volatile("ld.acquire.gpu.u32 %0, [%1];" : "=r"(cur) : "l"(&g_bar) : "memory");
            if ((int)(cur - target) >= 0) break;
            __nanosleep(32);
        }
    }
    __syncthreads();
}

// scalar rotpow (branch-free select), B bits: sincos(n*theta) from sincos(theta)
template <int B>
__device__ __forceinline__ void rotpow_s(float ps, float pc, unsigned n,
                                         float& so, float& co) {
    float s = 0.f, c = 1.f;
#pragma unroll
    for (int b = 0; b < B; b++) {
        float ns = fmaf(s, pc, c * ps);
        float nc = fmaf(c, pc, -s * ps);
        bool tk = (n >> b) & 1u;
        s = tk ? ns : s; c = tk ? nc : c;
        float t2 = 2.f * ps * pc;
        pc = fmaf(pc, pc, -ps * ps);
        ps = t2;
    }
    so = s; co = c;
}

// colmv: y[k] += sum_d shx[d]*W[d,k]; two 256-thread halves as vCTAs,
// 4-row chunks, double-buffered (R6-proven structure, x from shared)
__device__ __forceinline__ void colmv_sh(const float* __restrict__ W,
                                         const float* shx,
                                         float* __restrict__ y, int nvb,
                                         float* sh_acc) {
    int tid = threadIdx.x;
    int htid = tid & 255, half = tid >> 8;
    const float4* W4 = (const float4*)W;
    float4 acc = make_float4(0.f, 0.f, 0.f, 0.f);
    int vb = blockIdx.x * 2 + half;       // 0..295
    if (vb < nvb) {
        float4 w[4]; float xv[4];
#pragma unroll
        for (int i = 0; i < 4; i++) w[i] = __ldg(&W4[(size_t)(vb * 4 + i) * 256 + htid]);
#pragma unroll
        for (int i = 0; i < 4; i++) xv[i] = shx[vb * 4 + i];
        for (int nxt = vb + 2 * NBLK; ; nxt += 2 * NBLK) {
            float4 w2[4]; float xv2[4];
            bool more = nxt < nvb;
            if (more) {
#pragma unroll
                for (int i = 0; i < 4; i++) w2[i] = __ldg(&W4[(size_t)(nxt * 4 + i) * 256 + htid]);
#pragma unroll
                for (int i = 0; i < 4; i++) xv2[i] = shx[nxt * 4 + i];
            }
#pragma unroll
            for (int i = 0; i < 4; i++) {
                acc.x = fmaf(xv[i], w[i].x, acc.x);
                acc.y = fmaf(xv[i], w[i].y, acc.y);
                acc.z = fmaf(xv[i], w[i].z, acc.z);
                acc.w = fmaf(xv[i], w[i].w, acc.w);
            }
            if (!more) break;
#pragma unroll
            for (int i = 0; i < 4; i++) { w[i] = w2[i]; xv[i] = xv2[i]; }
        }
    }
    if (half == 1) ((float4*)sh_acc)[htid] = acc;
    __syncthreads();
    if (half == 0) {
        float4 o = ((float4*)sh_acc)[htid];
        atomicAdd(&y[4 * htid + 0], acc.x + o.x);
        atomicAdd(&y[4 * htid + 1], acc.y + o.y);
        atomicAdd(&y[4 * htid + 2], acc.z + o.z);
        atomicAdd(&y[4 * htid + 3], acc.w + o.w);
    }
}

// ---------------- pre kernel: trig tables, io/id, zeros ---------------------
__global__ void pre_kernel(const int* __restrict__ obs) {
    int g = blockIdx.x * blockDim.x + threadIdx.x;
    if (g < 2048) {
        double fij = exp(-(double)g * LN1E4_OVER_2048);
        double ds, dc;
        sincos(fij, &ds, &dc);
        g_fs1[g] = (float)ds; g_fc1[g] = (float)dc;
    }
    if (g < T * P) {
        const int* r0 = obs + (size_t)(2 * g) * NE;
        int io = 0, id = 0;
#pragma unroll
        for (int e = 0; e < NE; e++) {
            if (r0[e])      io = e;
            if (r0[NE + e]) id = e;
        }
        g_io[g] = io;
        g_id[g] = id;
    }
    if (g < DF) g_pc[g] = 0.f;
    if (g < DK) { g_q[g] = 0.f; g_ov[g] = 0.f; g_oacc[g] = 0.f; }
    if (g < 144) g_wtab[g] = 0.f;
    if (g == 0) g_Z = 0.f;
}

// ---------------- uber kernel ----------------------------------------------
__global__ void __launch_bounds__(NTHR, 1)
uber_kernel(const int* __restrict__ obs,
            const float* __restrict__ oe, const float* __restrict__ de,
            const float* __restrict__ WQ, const float* __restrict__ WK,
            const float* __restrict__ WV, const float* __restrict__ WO,
            const float* __restrict__ Wo, const float* __restrict__ bo,
            const float* __restrict__ Wd, const float* __restrict__ bd,
            const float* __restrict__ Wv, const float* __restrict__ bv,
            float* __restrict__ out, int out_size) {
    __shared__ float sbuf[7168];        // 28KB: [x 4096 | acc 1024] or sh_part[14][512]
    __shared__ float sh_tab[144];       // utab
    __shared__ float sh_wt[144];        // block wtab
    __shared__ float sh_e[32];
    __shared__ float sh_red[16];

    float* sh_x    = sbuf;
    float* sh_acc  = sbuf + 4096;
    float* sh_part = sbuf;

    int tid = threadIdx.x, bid = blockIdx.x;
    int wid = tid >> 5, lane = tid & 31;

    // ===== P1: build xlast in smem; q = xlast @ WQ ==========================
    for (int k = tid; k < DF; k += NTHR) {
        int d = k, p = d >> 9, r = d & 511;
        int row = 2 * ((T - 1) * P + p) + (r >= DM ? 1 : 0);
        const int* ro = obs + (size_t)row * NE;
        int idx = 0;
#pragma unroll
        for (int e = 0; e < NE; e++) if (ro[e]) idx = e;
        float ev = (r < DM) ? oe[idx * DM + r] : de[idx * DM + (r - DM)];
        int j = d >> 1;
        float s, c;
        rotpow_s<12>(g_fs1[j], g_fc1[j], T - 1, s, c);
        sh_x[k] = 16.0f * ev + ((d & 1) ? c : s);
    }
    __syncthreads();
    colmv_sh(WQ, sh_x, g_q, 1024, sh_acc);
    gridbar();

    // ===== P2: u = WK @ q  (warp per row, 16 rows per vb, prefetched) ======
    if (tid < 256) ((float4*)sbuf)[tid] = ((const float4*)g_q)[tid];
    __syncthreads();
    {
        int vb = bid;                       // nvb = 256
        if (vb < 256) {
            const float4* Wr = (const float4*)(WK + (size_t)(vb * 16 + wid) * DK);
            float4 w[8];
#pragma unroll
            for (int i = 0; i < 8; i++) w[i] = __ldg(&Wr[lane + 32 * i]);
            for (int nxt = vb + NBLK; ; nxt += NBLK) {
                float4 w2[8];
                bool more = nxt < 256;
                if (more) {
                    const float4* Wr2 = (const float4*)(WK + (size_t)(nxt * 16 + wid) * DK);
#pragma unroll
                    for (int i = 0; i < 8; i++) w2[i] = __ldg(&Wr2[lane + 32 * i]);
                }
                float acc = 0.f;
#pragma unroll
                for (int i = 0; i < 8; i++) {
                    float4 v = ((float4*)sbuf)[lane + 32 * i];
                    acc = fmaf(w[i].x, v.x, acc);
                    acc = fmaf(w[i].y, v.y, acc);
                    acc = fmaf(w[i].z, v.z, acc);
                    acc = fmaf(w[i].w, v.w, acc);
                }
#pragma unroll
                for (int o = 16; o; o >>= 1) acc += __shfl_xor_sync(0xffffffffu, acc, o);
                if (!lane) g_u[vb * 16 + wid] = acc;
                if (!more) break;
                vb = nxt;
#pragma unroll
                for (int i = 0; i < 8; i++) w[i] = w2[i];
            }
        }
    }
    gridbar();

    // ===== P34: fused scores + e + wtab + Z + pc (per 28-t block chunk) ====
    {
        int t0 = bid * 28;
        int nt = min(28, T - t0);
        if (nt > 0) {
            // utab: 144 emb-dot entries vs u (16 warps)
            for (int ent = wid; ent < 144; ent += 16) {
                int kind = ent / 72, p = (ent % 72) / 9, e = ent % 9;
                const float4* e4 = (const float4*)((kind ? de : oe) + e * DM);
                const float4* u4 = (const float4*)(g_u + p * 512 + kind * DM);
                float acc = 0.f;
#pragma unroll
                for (int i = 0; i < 2; i++) {
                    float4 a = __ldg(&e4[lane + 32 * i]);
                    float4 b = u4[lane + 32 * i];
                    acc += a.x * b.x + a.y * b.y + a.z * b.z + a.w * b.w;
                }
#pragma unroll
                for (int o = 16; o; o >>= 1) acc += __shfl_xor_sync(0xffffffffu, acc, o);
                if (!lane) sh_tab[ent] = acc;
            }
            if (tid < 144) sh_wt[tid] = 0.f;

            // seeds: thread owns j-pairs jp = tid + 512*q, q=0..3 (FULL 2048)
            float s[4], c[4], s1[4], c1[4], us[4], uc[4];
            float as[4] = {0.f, 0.f, 0.f, 0.f}, ac[4] = {0.f, 0.f, 0.f, 0.f};
#pragma unroll
            for (int q = 0; q < 4; q++) {
                int jp = tid + 512 * q;
                float2 u2 = ((const float2*)g_u)[jp];
                us[q] = u2.x; uc[q] = u2.y;
                s1[q] = g_fs1[jp]; c1[q] = g_fc1[jp];
                rotpow_s<12>(s1[q], c1[q], (unsigned)t0, s[q], c[q]);
            }
            __syncthreads();

            for (int sub = 0; sub < 28; sub += 14) {
                int cnt = min(14, nt - sub);
                if (cnt <= 0) break;
                float sv[4], cv[4];
#pragma unroll
                for (int q = 0; q < 4; q++) { sv[q] = s[q]; cv[q] = c[q]; }
                // sweep A: PE-dot partials
                for (int n = 0; n < cnt; n++) {
                    float part = 0.f;
#pragma unroll
                    for (int q = 0; q < 4; q++) {
                        part = fmaf(us[q], s[q], part);
                        part = fmaf(uc[q], c[q], part);
                    }
                    sh_part[n * 512 + tid] = part;
#pragma unroll
                    for (int q = 0; q < 4; q++) {
                        float ns = fmaf(s[q], c1[q], c[q] * s1[q]);
                        float nc = fmaf(c[q], c1[q], -s[q] * s1[q]);
                        s[q] = ns; c[q] = nc;
                    }
                }
                __syncthreads();
                // reduce rows -> scores -> e (no max subtraction: scores are O(10))
                {
                    int r = wid;
                    if (r < cnt) {
                        float v = 0.f;
#pragma unroll
                        for (int k = 0; k < 16; k++) v += sh_part[r * 512 + lane + 32 * k];
#pragma unroll
                        for (int o = 16; o; o >>= 1) v += __shfl_xor_sync(0xffffffffu, v, o);
                        if (!lane) {
                            int t = t0 + sub + r;
                            float es = 0.f;
#pragma unroll
                            for (int p = 0; p < P; p++)
                                es += sh_tab[p * 9 + g_io[t * P + p]]
                                    + sh_tab[72 + p * 9 + g_id[t * P + p]];
                            float sc = fmaf(16.0f, es, v);
                            sh_e[sub + r] = __expf(sc * (1.0f / 32.0f));
                        }
                    }
                }
                __syncthreads();
                // sweep B: e-weighted trig accumulation (rewind chains)
#pragma unroll
                for (int q = 0; q < 4; q++) { s[q] = sv[q]; c[q] = cv[q]; }
                for (int n = 0; n < cnt; n++) {
                    float e = sh_e[sub + n];
#pragma unroll
                    for (int q = 0; q < 4; q++) {
                        as[q] = fmaf(e, s[q], as[q]);
                        ac[q] = fmaf(e, c[q], ac[q]);
                        float ns = fmaf(s[q], c1[q], c[q] * s1[q]);
                        float nc = fmaf(c[q], c1[q], -s[q] * s1[q]);
                        s[q] = ns; c[q] = nc;
                    }
                }
                __syncthreads();
            }
            // pc scatter (spread addresses -> near REDG rate)
#pragma unroll
            for (int q = 0; q < 4; q++) {
                int jp = tid + 512 * q;
                atomicAdd(&g_pc[2 * jp],     as[q]);
                atomicAdd(&g_pc[2 * jp + 1], ac[q]);
            }
            // wtab + Z from sh_e
            if (tid < nt * 8) {
                int tt = tid >> 3, p = tid & 7;
                int t = t0 + tt;
                float w = sh_e[tt];
                atomicAdd(&sh_wt[p * 9 + g_io[t * P + p]], w);
                atomicAdd(&sh_wt[72 + p * 9 + g_id[t * P + p]], w);
            }
            __syncthreads();
            if (tid < 144) atomicAdd(&g_wtab[tid], sh_wt[tid]);
            if (wid == 0) {
                float z = (lane < nt) ? sh_e[lane] : 0.f;
                if (nt > 14) {
                    // lanes 0..13 also grab nothing extra; nt<=28<=32 so covered by lane<nt
                }
#pragma unroll
                for (int o = 16; o; o >>= 1) z += __shfl_xor_sync(0xffffffffu, z, o);
                if (!lane) atomicAdd(&g_Z, z);
            }
        }
    }
    gridbar();

    // ===== P5: build c in smem; ov = c @ WV ================================
    if (tid < 144) sh_tab[tid] = g_wtab[tid];
    __syncthreads();
    for (int k = tid; k < DF; k += NTHR) {
        int d = k, p = d >> 9, r = d & 511;
        float a = 0.f;
        if (r < DM) {
#pragma unroll
            for (int e = 0; e < NE; e++) a = fmaf(sh_tab[p * 9 + e], __ldg(&oe[e * DM + r]), a);
        } else {
            int rr = r - DM;
#pragma unroll
            for (int e = 0; e < NE; e++) a = fmaf(sh_tab[72 + p * 9 + e], __ldg(&de[e * DM + rr]), a);
        }
        sh_x[k] = fmaf(16.0f, a, g_pc[d]);
    }
    __syncthreads();
    colmv_sh(WV, sh_x, g_ov, 1024, sh_acc);
    gridbar();

    // ===== P6: oacc = ov @ WO ==============================================
    for (int k = tid; k < DK; k += NTHR) sh_x[k] = g_ov[k];
    __syncthreads();
    colmv_sh(WO, sh_x, g_oacc, 256, sh_acc);
    gridbar();

    // ===== P7: heads =======================================================
    if (bid < 129) {
        const float* Wr; float bias;
        if (bid < 64)       { Wr = Wo + bid * DK;        bias = bo[bid]; }
        else if (bid < 128) { Wr = Wd + (bid - 64) * DK; bias = bd[bid - 64]; }
        else                { Wr = Wv;                   bias = bv[0]; }
        float acc = 0.f;
        if (tid < 256) {
            float4 h4 = ((const float4*)g_oacc)[tid];
            float4 w4 = __ldg(&((const float4*)Wr)[tid]);
            acc = fmaxf(h4.x, 0.f) * w4.x + fmaxf(h4.y, 0.f) * w4.y +
                  fmaxf(h4.z, 0.f) * w4.z + fmaxf(h4.w, 0.f) * w4.w;
        }
#pragma unroll
        for (int o = 16; o; o >>= 1) acc += __shfl_xor_sync(0xffffffffu, acc, o);
        if (!lane && wid < 8) sh_red[wid] = acc;
        __syncthreads();
        if (tid == 0 && bid < out_size) {
            float sum = 0.f;
#pragma unroll
            for (int i = 0; i < 8; i++) sum += sh_red[i];
            out[bid] = sum * (1.0f / g_Z) + bias;
        }
    }
}

// ---------------- host launcher ---------------------------------------------
extern "C" void kernel_launch(void* const* d_in, const int* in_sizes, int n_in,
                              void* d_out, int out_size) {
    const int*   obs = (const int*)d_in[0];
    const float* oe  = (const float*)d_in[1];
    const float* de  = (const float*)d_in[2];
    const float* WQ  = (const float*)d_in[3];
    const float* WK  = (const float*)d_in[4];
    const float* WV  = (const float*)d_in[5];
    const float* WO  = (const float*)d_in[6];
    const float* Wo  = (const float*)d_in[7];
    const float* bo  = (const float*)d_in[8];
    const float* Wd  = (const float*)d_in[9];
    const float* bd  = (const float*)d_in[10];
    const float* Wv  = (const float*)d_in[11];
    const float* bv  = (const float*)d_in[12];
    float* out = (float*)d_out;

    pre_kernel<<<NBLK, 256>>>(obs);
    uber_kernel<<<NBLK, NTHR>>>(obs, oe, de, WQ, WK, WV, WO,
                                Wo, bo, Wd, bd, Wv, bv, out, out_size);
}

// round 13
// speedup vs baseline: 1.3006x; 1.0367x over previous
#include <cuda_runtime.h>
#include <math.h>

#define T      4096
#define P      8
#define DM     256
#define DF     4096
#define DK     1024
#define NE     9
#define NBLK   148
#define NTHR   512

// ---------------- scratch --------------------------------------------------
__device__ float    g_q[DK];
__device__ float    g_u[DF];
__device__ float    g_fs1[2048], g_fc1[2048];
__device__ float    g_wtab[144];
__device__ float    g_pc[DF];
__device__ float    g_ov[DK];
__device__ float    g_oacc[DK];
__device__ float    g_Z;
__device__ unsigned g_bar;          // monotonic, never reset

#define LN1E4_OVER_2048 (9.210340371976184 / 2048.0)

// leader-only-fence grid barrier, monotonic counter, pure spin
__device__ __forceinline__ void gridbar() {
    __syncthreads();
    if (threadIdx.x == 0) {
        asm volatile("fence.acq_rel.gpu;" ::: "memory");
        unsigned my = atomicAdd(&g_bar, 1u) + 1u;
        unsigned target = ((my + NBLK - 1u) / NBLK) * NBLK;
        unsigned cur;
        for (;;) {
            asm volatile("ld.acquire.gpu.u32 %0, [%1];" : "=r"(cur) : "l"(&g_bar) : "memory");
            if ((int)(cur - target) >= 0) break;
        }
    }
    __syncthreads();
}

// scalar rotpow (branch-free select), B bits: sincos(n*theta) from sincos(theta)
template <int B>
__device__ __forceinline__ void rotpow_s(float ps, float pc, unsigned n,
                                         float& so, float& co) {
    float s = 0.f, c = 1.f;
#pragma unroll
    for (int b = 0; b < B; b++) {
        float ns = fmaf(s, pc, c * ps);
        float nc = fmaf(c, pc, -s * ps);
        bool tk = (n >> b) & 1u;
        s = tk ? ns : s; c = tk ? nc : c;
        float t2 = 2.f * ps * pc;
        pc = fmaf(pc, pc, -ps * ps);
        ps = t2;
    }
    so = s; co = c;
}

// colmv: y[k] += sum_d shx[d]*W[d,k]; two 256-thread halves as vCTAs,
// 4-row chunks, double-buffered
__device__ __forceinline__ void colmv_sh(const float* __restrict__ W,
                                         const float* shx,
                                         float* __restrict__ y, int nvb,
                                         float* sh_acc) {
    int tid = threadIdx.x;
    int htid = tid & 255, half = tid >> 8;
    const float4* W4 = (const float4*)W;
    float4 acc = make_float4(0.f, 0.f, 0.f, 0.f);
    int vb = blockIdx.x * 2 + half;       // 0..295
    if (vb < nvb) {
        float4 w[4]; float xv[4];
#pragma unroll
        for (int i = 0; i < 4; i++) w[i] = __ldg(&W4[(size_t)(vb * 4 + i) * 256 + htid]);
#pragma unroll
        for (int i = 0; i < 4; i++) xv[i] = shx[vb * 4 + i];
        for (int nxt = vb + 2 * NBLK; ; nxt += 2 * NBLK) {
            float4 w2[4]; float xv2[4];
            bool more = nxt < nvb;
            if (more) {
#pragma unroll
                for (int i = 0; i < 4; i++) w2[i] = __ldg(&W4[(size_t)(nxt * 4 + i) * 256 + htid]);
#pragma unroll
                for (int i = 0; i < 4; i++) xv2[i] = shx[nxt * 4 + i];
            }
#pragma unroll
            for (int i = 0; i < 4; i++) {
                acc.x = fmaf(xv[i], w[i].x, acc.x);
                acc.y = fmaf(xv[i], w[i].y, acc.y);
                acc.z = fmaf(xv[i], w[i].z, acc.z);
                acc.w = fmaf(xv[i], w[i].w, acc.w);
            }
            if (!more) break;
#pragma unroll
            for (int i = 0; i < 4; i++) { w[i] = w2[i]; xv[i] = xv2[i]; }
        }
    }
    if (half == 1) ((float4*)sh_acc)[htid] = acc;
    __syncthreads();
    if (half == 0) {
        float4 o = ((float4*)sh_acc)[htid];
        atomicAdd(&y[4 * htid + 0], acc.x + o.x);
        atomicAdd(&y[4 * htid + 1], acc.y + o.y);
        atomicAdd(&y[4 * htid + 2], acc.z + o.z);
        atomicAdd(&y[4 * htid + 3], acc.w + o.w);
    }
}

// ---------------- pre kernel: trig tables + zeros ---------------------------
__global__ void pre_kernel() {
    int g = blockIdx.x * blockDim.x + threadIdx.x;   // 4096 threads
    if (g < 2048) {
        double fij = exp(-(double)g * LN1E4_OVER_2048);
        double ds, dc;
        sincos(fij, &ds, &dc);
        g_fs1[g] = (float)ds; g_fc1[g] = (float)dc;
    }
    if (g < DF) g_pc[g] = 0.f;
    if (g < DK) { g_q[g] = 0.f; g_ov[g] = 0.f; g_oacc[g] = 0.f; }
    if (g < 144) g_wtab[g] = 0.f;
    if (g == 0) g_Z = 0.f;
}

// ---------------- uber kernel ----------------------------------------------
__global__ void __launch_bounds__(NTHR, 1)
uber_kernel(const int* __restrict__ obs,
            const float* __restrict__ oe, const float* __restrict__ de,
            const float* __restrict__ WQ, const float* __restrict__ WK,
            const float* __restrict__ WV, const float* __restrict__ WO,
            const float* __restrict__ Wo, const float* __restrict__ bo,
            const float* __restrict__ Wd, const float* __restrict__ bd,
            const float* __restrict__ Wv, const float* __restrict__ bv,
            float* __restrict__ out, int out_size) {
    __shared__ float sbuf[7168];        // 28KB: [x 4096 | acc 1024] or sh_part[14][512]
    __shared__ float sh_tab[144];       // utab
    __shared__ float sh_wt[144];        // block wtab
    __shared__ float sh_e[32];
    __shared__ float sh_red[16];
    __shared__ int   sh_io[224], sh_id[224];

    float* sh_x    = sbuf;
    float* sh_acc  = sbuf + 4096;
    float* sh_part = sbuf;

    int tid = threadIdx.x, bid = blockIdx.x;
    int wid = tid >> 5, lane = tid & 31;

    // ===== P1: build xlast in smem; q = xlast @ WQ ==========================
    for (int k = tid; k < DF; k += NTHR) {
        int d = k, p = d >> 9, r = d & 511;
        int row = 2 * ((T - 1) * P + p) + (r >= DM ? 1 : 0);
        const int* ro = obs + (size_t)row * NE;
        int idx = 0;
#pragma unroll
        for (int e = 0; e < NE; e++) if (ro[e]) idx = e;
        float ev = (r < DM) ? oe[idx * DM + r] : de[idx * DM + (r - DM)];
        int j = d >> 1;
        float s, c;
        rotpow_s<12>(g_fs1[j], g_fc1[j], T - 1, s, c);
        sh_x[k] = 16.0f * ev + ((d & 1) ? c : s);
    }
    __syncthreads();
    colmv_sh(WQ, sh_x, g_q, 1024, sh_acc);
    gridbar();

    // ===== P2: u = WK @ q  (warp per row, 16 rows per vb, prefetched) ======
    if (tid < 256) ((float4*)sbuf)[tid] = ((const float4*)g_q)[tid];
    __syncthreads();
    {
        int vb = bid;                       // nvb = 256
        if (vb < 256) {
            const float4* Wr = (const float4*)(WK + (size_t)(vb * 16 + wid) * DK);
            float4 w[8];
#pragma unroll
            for (int i = 0; i < 8; i++) w[i] = __ldg(&Wr[lane + 32 * i]);
            for (int nxt = vb + NBLK; ; nxt += NBLK) {
                float4 w2[8];
                bool more = nxt < 256;
                if (more) {
                    const float4* Wr2 = (const float4*)(WK + (size_t)(nxt * 16 + wid) * DK);
#pragma unroll
                    for (int i = 0; i < 8; i++) w2[i] = __ldg(&Wr2[lane + 32 * i]);
                }
                float acc = 0.f;
#pragma unroll
                for (int i = 0; i < 8; i++) {
                    float4 v = ((float4*)sbuf)[lane + 32 * i];
                    acc = fmaf(w[i].x, v.x, acc);
                    acc = fmaf(w[i].y, v.y, acc);
                    acc = fmaf(w[i].z, v.z, acc);
                    acc = fmaf(w[i].w, v.w, acc);
                }
#pragma unroll
                for (int o = 16; o; o >>= 1) acc += __shfl_xor_sync(0xffffffffu, acc, o);
                if (!lane) g_u[vb * 16 + wid] = acc;
                if (!more) break;
                vb = nxt;
#pragma unroll
                for (int i = 0; i < 8; i++) w[i] = w2[i];
            }
        }
    }
    gridbar();

    // ===== P34: fused scores + e + wtab + Z + pc ===========================
    {
        int t0 = bid * 28;
        int nt = min(28, T - t0);
        if (nt > 0) {
            // local io/id decode for this block's 28 x 8 (t,p) pairs
            if (tid < nt * 8) {
                int tt = tid >> 3, p = tid & 7;
                int t = t0 + tt;
                const int* r0 = obs + (size_t)(2 * (t * P + p)) * NE;
                int io = 0, id = 0;
#pragma unroll
                for (int e = 0; e < NE; e++) {
                    if (r0[e])      io = e;
                    if (r0[NE + e]) id = e;
                }
                sh_io[tid] = io;
                sh_id[tid] = id;
            }
            // utab: 144 emb-dot entries vs u (16 warps)
            for (int ent = wid; ent < 144; ent += 16) {
                int kind = ent / 72, p = (ent % 72) / 9, e = ent % 9;
                const float4* e4 = (const float4*)((kind ? de : oe) + e * DM);
                const float4* u4 = (const float4*)(g_u + p * 512 + kind * DM);
                float acc = 0.f;
#pragma unroll
                for (int i = 0; i < 2; i++) {
                    float4 a = __ldg(&e4[lane + 32 * i]);
                    float4 b = u4[lane + 32 * i];
                    acc += a.x * b.x + a.y * b.y + a.z * b.z + a.w * b.w;
                }
#pragma unroll
                for (int o = 16; o; o >>= 1) acc += __shfl_xor_sync(0xffffffffu, acc, o);
                if (!lane) sh_tab[ent] = acc;
            }
            if (tid < 144) sh_wt[tid] = 0.f;

            // seeds: thread owns jp = tid + 512*q, q=0..3 (full 2048 freqs)
            float v[4], w[4], s0[4], c0[4], s1[4], c1[4], y1[4], y2[4];
            float as[4] = {0.f, 0.f, 0.f, 0.f}, ac[4] = {0.f, 0.f, 0.f, 0.f};
#pragma unroll
            for (int q = 0; q < 4; q++) {
                int jp = tid + 512 * q;
                float2 u2 = ((const float2*)g_u)[jp];
                s1[q] = g_fs1[jp]; c1[q] = g_fc1[jp];
                rotpow_s<12>(s1[q], c1[q], (unsigned)t0, s0[q], c0[q]);
                v[q] = fmaf(u2.x, s0[q],  u2.y * c0[q]);   // us*s + uc*c
                w[q] = fmaf(u2.x, c0[q], -u2.y * s0[q]);   // us*c - uc*s
                y1[q] = 0.f; y2[q] = 0.f;
            }
            __syncthreads();

            for (int sub = 0; sub < 28; sub += 14) {
                int cnt = min(14, nt - sub);
                if (cnt <= 0) break;
                // sweep A: amplitude-phase chains; part = sum v
                for (int n = 0; n < cnt; n++) {
                    sh_part[n * 512 + tid] = (v[0] + v[1]) + (v[2] + v[3]);
#pragma unroll
                    for (int q = 0; q < 4; q++) {
                        float nv = fmaf(c1[q], v[q],  s1[q] * w[q]);
                        float nw = fmaf(c1[q], w[q], -s1[q] * v[q]);
                        v[q] = nv; w[q] = nw;
                    }
                }
                __syncthreads();
                // reduce rows -> scores -> e (no max subtraction; scores O(10))
                {
                    int r = wid;
                    if (r < cnt) {
                        float vv = 0.f;
#pragma unroll
                        for (int k = 0; k < 16; k++) vv += sh_part[r * 512 + lane + 32 * k];
#pragma unroll
                        for (int o = 16; o; o >>= 1) vv += __shfl_xor_sync(0xffffffffu, vv, o);
                        if (!lane) {
                            int base = (sub + r) * 8;
                            float es = 0.f;
#pragma unroll
                            for (int p = 0; p < P; p++)
                                es += sh_tab[p * 9 + sh_io[base + p]]
                                    + sh_tab[72 + p * 9 + sh_id[base + p]];
                            float sc = fmaf(16.0f, es, vv);
                            sh_e[sub + r] = __expf(sc * (1.0f / 32.0f));
                        }
                    }
                }
                __syncthreads();
                // sweep B: Goertzel per q over this chunk's e values
                for (int n = 0; n < cnt; n++) {
                    float e = sh_e[sub + n];
#pragma unroll
                    for (int q = 0; q < 4; q++) {
                        float yn = fmaf(2.f * c1[q], y1[q], e - y2[q]);
                        y2[q] = y1[q]; y1[q] = yn;
                    }
                }
                // endgame per q: extract A,B, rotate into absolute phase
#pragma unroll
                for (int q = 0; q < 4; q++) {
                    float sN, cN;
                    rotpow_s<4>(s1[q], c1[q], (unsigned)cnt, sN, cN);
                    float sNm1 = fmaf(sN, c1[q], -cN * s1[q]);
                    float cNm1 = fmaf(cN, c1[q],  sN * s1[q]);
                    float A = fmaf(sNm1, y1[q], -sN * y2[q]);
                    float B = fmaf(cNm1, y1[q], -cN * y2[q]);
                    as[q] += fmaf(s0[q], B,  c0[q] * A);
                    ac[q] += fmaf(c0[q], B, -s0[q] * A);
                    // advance chunk phase by cnt steps
                    float ns0 = fmaf(s0[q], cN,  c0[q] * sN);
                    float nc0 = fmaf(c0[q], cN, -s0[q] * sN);
                    s0[q] = ns0; c0[q] = nc0;
                    y1[q] = 0.f; y2[q] = 0.f;
                }
            }
            // pc scatter (spread addresses)
#pragma unroll
            for (int q = 0; q < 4; q++) {
                int jp = tid + 512 * q;
                atomicAdd(&g_pc[2 * jp],     as[q]);
                atomicAdd(&g_pc[2 * jp + 1], ac[q]);
            }
            // wtab + Z from sh_e
            if (tid < nt * 8) {
                int tt = tid >> 3, p = tid & 7;
                float ww = sh_e[tt];
                atomicAdd(&sh_wt[p * 9 + sh_io[tid]], ww);
                atomicAdd(&sh_wt[72 + p * 9 + sh_id[tid]], ww);
            }
            __syncthreads();
            if (tid < 144) atomicAdd(&g_wtab[tid], sh_wt[tid]);
            if (wid == 0) {
                float z = (lane < nt) ? sh_e[lane] : 0.f;
#pragma unroll
                for (int o = 16; o; o >>= 1) z += __shfl_xor_sync(0xffffffffu, z, o);
                if (!lane) atomicAdd(&g_Z, z);
            }
        }
    }
    gridbar();

    // ===== P5: build c in smem; ov = c @ WV ================================
    if (tid < 144) sh_tab[tid] = g_wtab[tid];
    __syncthreads();
    for (int k = tid; k < DF; k += NTHR) {
        int d = k, p = d >> 9, r = d & 511;
        float a = 0.f;
        if (r < DM) {
#pragma unroll
            for (int e = 0; e < NE; e++) a = fmaf(sh_tab[p * 9 + e], __ldg(&oe[e * DM + r]), a);
        } else {
            int rr = r - DM;
#pragma unroll
            for (int e = 0; e < NE; e++) a = fmaf(sh_tab[72 + p * 9 + e], __ldg(&de[e * DM + rr]), a);
        }
        sh_x[k] = fmaf(16.0f, a, g_pc[d]);
    }
    __syncthreads();
    colmv_sh(WV, sh_x, g_ov, 1024, sh_acc);
    gridbar();

    // ===== P6: oacc = ov @ WO ==============================================
    for (int k = tid; k < DK; k += NTHR) sh_x[k] = g_ov[k];
    __syncthreads();
    colmv_sh(WO, sh_x, g_oacc, 256, sh_acc);
    gridbar();

    // ===== P7: heads =======================================================
    if (bid < 129) {
        const float* Wr; float bias;
        if (bid < 64)       { Wr = Wo + bid * DK;        bias = bo[bid]; }
        else if (bid < 128) { Wr = Wd + (bid - 64) * DK; bias = bd[bid - 64]; }
        else                { Wr = Wv;                   bias = bv[0]; }
        float acc = 0.f;
        if (tid < 256) {
            float4 h4 = ((const float4*)g_oacc)[tid];
            float4 w4 = __ldg(&((const float4*)Wr)[tid]);
            acc = fmaxf(h4.x, 0.f) * w4.x + fmaxf(h4.y, 0.f) * w4.y +
                  fmaxf(h4.z, 0.f) * w4.z + fmaxf(h4.w, 0.f) * w4.w;
        }
#pragma unroll
        for (int o = 16; o; o >>= 1) acc += __shfl_xor_sync(0xffffffffu, acc, o);
        if (!lane && wid < 8) sh_red[wid] = acc;
        __syncthreads();
        if (tid == 0 && bid < out_size) {
            float sum = 0.f;
#pragma unroll
            for (int i = 0; i < 8; i++) sum += sh_red[i];
            out[bid] = sum * (1.0f / g_Z) + bias;
        }
    }
}

// ---------------- host launcher ---------------------------------------------
extern "C" void kernel_launch(void* const* d_in, const int* in_sizes, int n_in,
                              void* d_out, int out_size) {
    const int*   obs = (const int*)d_in[0];
    const float* oe  = (const float*)d_in[1];
    const float* de  = (const float*)d_in[2];
    const float* WQ  = (const float*)d_in[3];
    const float* WK  = (const float*)d_in[4];
    const float* WV  = (const float*)d_in[5];
    const float* WO  = (const float*)d_in[6];
    const float* Wo  = (const float*)d_in[7];
    const float* bo  = (const float*)d_in[8];
    const float* Wd  = (const float*)d_in[9];
    const float* bd  = (const float*)d_in[10];
    const float* Wv  = (const float*)d_in[11];
    const float* bv  = (const float*)d_in[12];
    float* out = (float*)d_out;

    pre_kernel<<<16, 256>>>();
    uber_kernel<<<NBLK, NTHR>>>(obs, oe, de, WQ, WK, WV, WO,
                                Wo, bo, Wd, bd, Wv, bv, out, out_size);
}